// round 8
// baseline (speedup 1.0000x reference)
#include <cuda_runtime.h>

// Net_2095944040841: 3-layer LSTM (reference's buggy c-state wiring) on GB300.
// R8: unit-owner fusion (gates+activation+update in-register, 3 barriers/step)
// with FULL double-buffered state (x,h1,h2,h3 by step parity) -> race-free.
// Cell3 f-gate eliminated (c3==0). Biases in registers. W1 staged in WB region.

#define T_LEN 1024
#define IN_D  20
#define HIDN  50
#define OUT_D 8
#define NB    4
#define NCTA  128
#define NTH   160

// shared memory layout (float offsets)
#define WA_STR 72            // cell1 row: 20 fused-x cols + 52 h cols (2 zero-pad)
#define WB_STR 104           // cells2/3 row: 52 + 52 cols (2 zero-pad each)
#define WA_OFF 0             // 200 x 72
#define WB_OFF 14400         // 200 x 104
#define WC_OFF 35200         // 200 x 104
#define W2_OFF 56000         // 8 x 50
#define X_OFF  56400         // 2 x 80  (x buffers, parity-indexed)
#define H1_OFF 56560         // 2 x 208 (26 pairs, pair 25 = zero pad)
#define H2_OFF 56976         // 2 x 208
#define H3_OFF 57392         // 2 x 208
#define SMEM_FLT 57808       // 231,232 bytes

typedef unsigned long long ull;

static __device__ __forceinline__ void upk(ull v, float &a, float &b) {
    asm("mov.b64 {%0,%1}, %2;" : "=f"(a), "=f"(b) : "l"(v));
}
static __device__ __forceinline__ ull fma2(ull a, ull b, ull c) {
    ull d; asm("fma.rn.f32x2 %0, %1, %2, %3;" : "=l"(d) : "l"(a), "l"(b), "l"(c)); return d;
}
static __device__ __forceinline__ float tanhap(float x) {
    float t; asm("tanh.approx.f32 %0, %1;" : "=f"(t) : "f"(x)); return t;
}
static __device__ __forceinline__ float sigm(float x) {
    return fmaf(tanhap(0.5f * x), 0.5f, 0.5f);
}

// All gates of one unit for one batch-pair. Weight row = [part1 NQ1 chunks |
// part2 NQ2 chunks] contiguous; inputs come from two independent regions
// (each already offset by bpo). One chunk = 4 columns = 2 interleaved pairs.
template<int NQ1, int NQ2, bool HASF>
static __device__ __forceinline__ void unit_gates(
    const float* __restrict__ wi, const float* __restrict__ wf,
    const float* __restrict__ wg, const float* __restrict__ wo,
    const float* __restrict__ in1, const float* __restrict__ in2,
    float bi, float bf, float bg, float bo,
    float* __restrict__ iv, float* __restrict__ fv,
    float* __restrict__ gv, float* __restrict__ ov)
{
    const ulonglong2* wiq = reinterpret_cast<const ulonglong2*>(wi);
    const ulonglong2* wfq = reinterpret_cast<const ulonglong2*>(wf);
    const ulonglong2* wgq = reinterpret_cast<const ulonglong2*>(wg);
    const ulonglong2* woq = reinterpret_cast<const ulonglong2*>(wo);
    ull ai0 = 0, ai1 = 0, af0 = 0, af1 = 0;
    ull ag0 = 0, ag1 = 0, ao0 = 0, ao1 = 0;
#pragma unroll
    for (int kk = 0; kk < NQ1 + NQ2; kk++) {
        const float* src = (kk < NQ1) ? (in1 + 16 * kk) : (in2 + 16 * (kk - NQ1));
        ulonglong2 qa = *reinterpret_cast<const ulonglong2*>(src);
        ulonglong2 qb = *reinterpret_cast<const ulonglong2*>(src + 8);
        ulonglong2 wI = wiq[kk];
        ulonglong2 wG = wgq[kk];
        ulonglong2 wO = woq[kk];
        ai0 = fma2(wI.x, qa.x, ai0); ai1 = fma2(wI.x, qa.y, ai1);
        ai0 = fma2(wI.y, qb.x, ai0); ai1 = fma2(wI.y, qb.y, ai1);
        ag0 = fma2(wG.x, qa.x, ag0); ag1 = fma2(wG.x, qa.y, ag1);
        ag0 = fma2(wG.y, qb.x, ag0); ag1 = fma2(wG.y, qb.y, ag1);
        ao0 = fma2(wO.x, qa.x, ao0); ao1 = fma2(wO.x, qa.y, ao1);
        ao0 = fma2(wO.y, qb.x, ao0); ao1 = fma2(wO.y, qb.y, ao1);
        if (HASF) {
            ulonglong2 wF = wfq[kk];
            af0 = fma2(wF.x, qa.x, af0); af1 = fma2(wF.x, qa.y, af1);
            af0 = fma2(wF.y, qb.x, af0); af1 = fma2(wF.y, qb.y, af1);
        }
    }
    float lo, hi;
    upk(ai0, lo, hi); iv[0] = sigm(lo + hi + bi);
    upk(ai1, lo, hi); iv[1] = sigm(lo + hi + bi);
    upk(ag0, lo, hi); gv[0] = tanhap(lo + hi + bg);
    upk(ag1, lo, hi); gv[1] = tanhap(lo + hi + bg);
    upk(ao0, lo, hi); ov[0] = sigm(lo + hi + bo);
    upk(ao1, lo, hi); ov[1] = sigm(lo + hi + bo);
    if (HASF) {
        upk(af0, lo, hi); fv[0] = sigm(lo + hi + bf);
        upk(af1, lo, hi); fv[1] = sigm(lo + hi + bf);
    }
}

extern __shared__ float sm[];

__global__ void __launch_bounds__(NTH, 1)
lstm_persist_kernel(const float* __restrict__ x,
                    const float* __restrict__ W1,   const float* __restrict__ b1,
                    const float* __restrict__ Wih1, const float* __restrict__ Whh1,
                    const float* __restrict__ bih1, const float* __restrict__ bhh1,
                    const float* __restrict__ Wih2, const float* __restrict__ Whh2,
                    const float* __restrict__ bih2, const float* __restrict__ bhh2,
                    const float* __restrict__ Wih3, const float* __restrict__ Whh3,
                    const float* __restrict__ bih3, const float* __restrict__ bhh3,
                    const float* __restrict__ W2,   const float* __restrict__ b2,
                    float* __restrict__ out)
{
    const int tid = threadIdx.x;
    const int b0  = blockIdx.x * NB;

    // ---------------- init ----------------
    // stage W1 (1000 floats) inside the not-yet-filled WB region (in bounds)
    for (int i = tid; i < HIDN * IN_D; i += NTH) sm[WB_OFF + i] = W1[i];
    __syncthreads();

    // WA x-part: Wc[r][k] = sum_j Wih1[r][j] * W1[j][k]
    for (int i = tid; i < 200 * IN_D; i += NTH) {
        int r = i / IN_D, k = i % IN_D;
        float acc = 0.f;
#pragma unroll 10
        for (int j = 0; j < HIDN; j++)
            acc += Wih1[r * HIDN + j] * sm[WB_OFF + j * IN_D + k];
        sm[WA_OFF + r * WA_STR + k] = acc;
    }
    // WA h-part (52 cols, last 2 zero)
    for (int i = tid; i < 200 * 52; i += NTH) {
        int r = i / 52, c = i % 52;
        sm[WA_OFF + r * WA_STR + IN_D + c] = (c < HIDN) ? Whh1[r * HIDN + c] : 0.f;
    }
    __syncthreads();   // staging reads complete before WB fill

    // WB/WC rows: [Wih (52, pad) | Whh (52, pad)]
    for (int i = tid; i < 200 * WB_STR; i += NTH) {
        int r = i / WB_STR, c = i % WB_STR;
        float vb, vc;
        if (c < 52) {
            vb = (c < HIDN) ? Wih2[r * HIDN + c] : 0.f;
            vc = (c < HIDN) ? Wih3[r * HIDN + c] : 0.f;
        } else {
            int cc = c - 52;
            vb = (cc < HIDN) ? Whh2[r * HIDN + cc] : 0.f;
            vc = (cc < HIDN) ? Whh3[r * HIDN + cc] : 0.f;
        }
        sm[WB_OFF + i] = vb;
        sm[WC_OFF + i] = vc;
    }
    for (int i = tid; i < OUT_D * HIDN; i += NTH) sm[W2_OFF + i] = W2[i];

    // zero all state regions (x, h1, h2, h3; both parities incl. pad pairs)
    for (int i = tid; i < 1408; i += NTH) sm[X_OFF + i] = 0.f;
    __syncthreads();
    // x(0) into parity-1 x buffer (step 0 reads parity 1)
    if (tid < NB * IN_D) {
        int b = tid / IN_D, k = tid % IN_D;
        sm[X_OFF + 80 + (k >> 1) * 8 + 2 * b + (k & 1)] =
            x[((size_t)(b0 + b) * T_LEN) * IN_D + k];
    }
    __syncthreads();

    // ---------------- role setup ----------------
    const int lane = tid & 31, wrp = tid >> 5;
    const bool isgate = (wrp < 4) && (lane < 25);
    const int task = wrp * 25 + lane;           // 0..99
    const int u  = task % 50;                   // hidden unit
    const int bp = task / 50;                   // batch-pair: batches 2bp, 2bp+1
    const bool ishelp = (wrp == 4);
    const int u7 = tid - 128;
    const int e0 = u7, e1 = u7 + 32, e2 = u7 + 64;
    const int ob = u7 >> 3, oo = u7 & 7;

    // weight row pointers
    const float* wa_i = sm + WA_OFF + u * WA_STR;
    const float* wa_f = wa_i + 50 * WA_STR;
    const float* wa_g = wa_i + 100 * WA_STR;
    const float* wa_o = wa_i + 150 * WA_STR;
    const float* wb_i = sm + WB_OFF + u * WB_STR;
    const float* wb_f = wb_i + 50 * WB_STR;
    const float* wb_g = wb_i + 100 * WB_STR;
    const float* wb_o = wb_i + 150 * WB_STR;
    const float* wc_i = sm + WC_OFF + u * WB_STR;
    const float* wc_g = wc_i + 100 * WB_STR;
    const float* wc_o = wc_i + 150 * WB_STR;

    // fused biases from global (registers)
    float bai = 0, baf = 0, bag = 0, bao = 0;
    float bbi = 0, bbf = 0, bbg = 0, bbo = 0;
    float bci = 0, bcg = 0, bco = 0;
    if (isgate) {
        bai = bih1[u] + bhh1[u];
        baf = bih1[u + 50] + bhh1[u + 50];
        bag = bih1[u + 100] + bhh1[u + 100];
        bao = bih1[u + 150] + bhh1[u + 150];
        for (int j = 0; j < HIDN; j++) {
            float bj = b1[j];
            bai += Wih1[u * HIDN + j] * bj;
            baf += Wih1[(u + 50) * HIDN + j] * bj;
            bag += Wih1[(u + 100) * HIDN + j] * bj;
            bao += Wih1[(u + 150) * HIDN + j] * bj;
        }
        bbi = bih2[u] + bhh2[u];
        bbf = bih2[u + 50] + bhh2[u + 50];
        bbg = bih2[u + 100] + bhh2[u + 100];
        bbo = bih2[u + 150] + bhh2[u + 150];
        bci = bih3[u] + bhh3[u];
        bcg = bih3[u + 100] + bhh3[u + 100];
        bco = bih3[u + 150] + bhh3[u + 150];
    }
    float b2r = 0.f;
    if (ishelp) b2r = b2[oo];

    const int up8 = (u >> 1) * 8 + (u & 1);     // pair-layout base for unit u
    const int bpo = bp * 4;                     // batch-pair offset within a pair
    float c1s[2] = {0.f, 0.f};                  // cell1 state, batches 2bp, 2bp+1
    float czs[2] = {0.f, 0.f};                  // cell3 c_new (acts as c2 next step)
    float iv[2], fv[2], gv[2], ov[2];

    // ---------------- main recurrent loop (3 barriers/step) ----------------
    for (int t = 0; t < T_LEN; t++) {
        const int q = t & 1;          // write parity; reads use 1-q
        const int rq = 1 - q;

        // ---- phase A: cell1 gates+update || helper {x(t+1)->x[q], out(t-1)} ----
        if (isgate) {
            unit_gates<5, 13, true>(wa_i, wa_f, wa_g, wa_o,
                                    sm + X_OFF + rq * 80 + bpo,
                                    sm + H1_OFF + rq * 208 + bpo,
                                    bai, baf, bag, bao, iv, fv, gv, ov);
#pragma unroll
            for (int k = 0; k < 2; k++) {
                int b = 2 * bp + k;
                c1s[k] = fv[k] * c1s[k] + iv[k] * gv[k];
                sm[H1_OFF + q * 208 + up8 + 2 * b] = ov[k] * tanhap(c1s[k]);
            }
        } else if (ishelp) {
            float xv0 = 0.f, xv1 = 0.f, xv2 = 0.f;
            const bool xl = (t + 1 < T_LEN);
            if (xl) {
                { int b = e0 / IN_D, k = e0 % IN_D;
                  xv0 = x[((size_t)(b0 + b) * T_LEN + (t + 1)) * IN_D + k]; }
                { int b = e1 / IN_D, k = e1 % IN_D;
                  xv1 = x[((size_t)(b0 + b) * T_LEN + (t + 1)) * IN_D + k]; }
                if (e2 < NB * IN_D) {
                  int b = e2 / IN_D, k = e2 % IN_D;
                  xv2 = x[((size_t)(b0 + b) * T_LEN + (t + 1)) * IN_D + k]; }
            }
            if (t > 0) {   // out-projection for step t-1 from h3[1-q]
                float acc = b2r;
                const float* h3p = sm + H3_OFF + rq * 208;
#pragma unroll
                for (int j = 0; j < HIDN; j++)
                    acc += sm[W2_OFF + oo * HIDN + j] *
                           h3p[(j >> 1) * 8 + 2 * ob + (j & 1)];
                out[((size_t)(b0 + ob) * T_LEN + (t - 1)) * OUT_D + oo] = acc;
            }
            if (xl) {      // store x(t+1) into x[q] (read at step t+1)
                { int b = e0 / IN_D, k = e0 % IN_D;
                  sm[X_OFF + q * 80 + (k >> 1) * 8 + 2 * b + (k & 1)] = xv0; }
                { int b = e1 / IN_D, k = e1 % IN_D;
                  sm[X_OFF + q * 80 + (k >> 1) * 8 + 2 * b + (k & 1)] = xv1; }
                if (e2 < NB * IN_D) {
                  int b = e2 / IN_D, k = e2 % IN_D;
                  sm[X_OFF + q * 80 + (k >> 1) * 8 + 2 * b + (k & 1)] = xv2; }
            }
        }
        __syncthreads();

        // ---- phase B: cell2 gates+update (reads h1[q], h2[1-q]) ----
        if (isgate) {
            unit_gates<13, 13, true>(wb_i, wb_f, wb_g, wb_o,
                                     sm + H1_OFF + q * 208 + bpo,
                                     sm + H2_OFF + rq * 208 + bpo,
                                     bbi, bbf, bbg, bbo, iv, fv, gv, ov);
#pragma unroll
            for (int k = 0; k < 2; k++) {
                int b = 2 * bp + k;
                float c2t = fv[k] * czs[k] + iv[k] * gv[k];
                sm[H2_OFF + q * 208 + up8 + 2 * b] = ov[k] * tanhap(c2t);
            }
        }
        __syncthreads();

        // ---- phase C: cell3 gates+update (no f-gate: c3 == 0) ----
        if (isgate) {
            unit_gates<13, 13, false>(wc_i, wc_i /*unused*/, wc_g, wc_o,
                                      sm + H2_OFF + q * 208 + bpo,
                                      sm + H3_OFF + rq * 208 + bpo,
                                      bci, 0.f, bcg, bco, iv, fv, gv, ov);
#pragma unroll
            for (int k = 0; k < 2; k++) {
                int b = 2 * bp + k;
                czs[k] = iv[k] * gv[k];
                sm[H3_OFF + q * 208 + up8 + 2 * b] = ov[k] * tanhap(czs[k]);
            }
        }
        __syncthreads();
    }

    // tail: out-projection for the final step (written with parity 1)
    if (ishelp) {
        float acc = b2r;
        const float* h3p = sm + H3_OFF + ((T_LEN - 1) & 1) * 208;
#pragma unroll
        for (int j = 0; j < HIDN; j++)
            acc += sm[W2_OFF + oo * HIDN + j] *
                   h3p[(j >> 1) * 8 + 2 * ob + (j & 1)];
        out[((size_t)(b0 + ob) * T_LEN + (T_LEN - 1)) * OUT_D + oo] = acc;
    }
}

extern "C" void kernel_launch(void* const* d_in, const int* in_sizes, int n_in,
                              void* d_out, int out_size)
{
    const float* x    = (const float*)d_in[0];
    const float* W1   = (const float*)d_in[1];
    const float* b1   = (const float*)d_in[2];
    const float* Wih1 = (const float*)d_in[3];
    const float* Whh1 = (const float*)d_in[4];
    const float* bih1 = (const float*)d_in[5];
    const float* bhh1 = (const float*)d_in[6];
    const float* Wih2 = (const float*)d_in[7];
    const float* Whh2 = (const float*)d_in[8];
    const float* bih2 = (const float*)d_in[9];
    const float* bhh2 = (const float*)d_in[10];
    const float* Wih3 = (const float*)d_in[11];
    const float* Whh3 = (const float*)d_in[12];
    const float* bih3 = (const float*)d_in[13];
    const float* bhh3 = (const float*)d_in[14];
    const float* W2   = (const float*)d_in[15];
    const float* b2   = (const float*)d_in[16];
    float* out = (float*)d_out;

    const int smem_bytes = SMEM_FLT * sizeof(float);  // 231,232
    cudaFuncSetAttribute(lstm_persist_kernel,
                         cudaFuncAttributeMaxDynamicSharedMemorySize, smem_bytes);

    lstm_persist_kernel<<<NCTA, NTH, smem_bytes>>>(
        x, W1, b1, Wih1, Whh1, bih1, bhh1,
        Wih2, Whh2, bih2, bhh2, Wih3, Whh3, bih3, bhh3,
        W2, b2, out);
}

// round 9
// speedup vs baseline: 1.6529x; 1.6529x over previous
#include <cuda_runtime.h>

// Net_2095944040841: 3-layer LSTM (reference's buggy c-state wiring) on GB300.
// R9: 8 gate warps (2/SMSP). Lane = (half | bp | u). bp-pairs share weight
// addresses in-warp (broadcast, 1x weight traffic); column-halves combine via
// one shfl.xor(16). 3 barriers/step, fused gates+update, cell3 f-gate dead.

#define T_LEN 1024
#define IN_D  20
#define HIDN  50
#define OUT_D 8
#define NB    4
#define NCTA  128
#define NTH   256

// shared memory layout (float offsets)
#define WA_STR 76            // cell1 row: 20 fused-x + 52 h1 cols (+4 pad)
#define WB_STR 108           // cells2/3 row: 52 + 52 cols (+4 pad)
#define WA_OFF 0             // 200 x 76                  -> 15200
#define WB_OFF 15200         // 200 x 108                 -> 36800
#define WC_OFF 36800         // 150 x 108 (i,g,o rows)    -> 53000
#define W2_OFF 53000         // 8 x 50                    -> 53400
#define XH1_OFF 53400        // 2 x 288: [x(80)|h1(208)] per parity -> 53976
#define C2_OFF  53976        // [h1[0]|h2a[1]|h1[1]|h2a[0]] 4x208   -> 54808
#define C3_OFF  54808        // [h2b[0]|h3[1]|h2b[1]|h3[0]] 4x208   -> 55640
#define SMEM_FLT 55640       // 222,560 bytes

typedef unsigned long long ull;

static __device__ __forceinline__ void upk(ull v, float &a, float &b) {
    asm("mov.b64 {%0,%1}, %2;" : "=f"(a), "=f"(b) : "l"(v));
}
static __device__ __forceinline__ ull fma2(ull a, ull b, ull c) {
    ull d; asm("fma.rn.f32x2 %0, %1, %2, %3;" : "=l"(d) : "l"(a), "l"(b), "l"(c)); return d;
}
static __device__ __forceinline__ ull add2(ull a, ull b) {
    ull d; asm("add.rn.f32x2 %0, %1, %2;" : "=l"(d) : "l"(a), "l"(b)); return d;
}
static __device__ __forceinline__ float tanhap(float x) {
    float t; asm("tanh.approx.f32 %0, %1;" : "=f"(t) : "f"(x)); return t;
}
static __device__ __forceinline__ float sigm(float x) {
    return fmaf(tanhap(0.5f * x), 0.5f, 0.5f);
}

// Half-GEMV: NQ chunks (4 cols each) of 4 (or 3) gate rows x 2 batches.
template<int NQ, bool HASF>
static __device__ __forceinline__ void gemv_half(
    const float* __restrict__ wi, const float* __restrict__ wf,
    const float* __restrict__ wg, const float* __restrict__ wo,
    const float* __restrict__ inp,
    ull &ai0, ull &ai1, ull &af0, ull &af1,
    ull &ag0, ull &ag1, ull &ao0, ull &ao1)
{
#pragma unroll
    for (int kk = 0; kk < NQ; kk++) {
        ulonglong2 qa = *reinterpret_cast<const ulonglong2*>(inp + 16 * kk);
        ulonglong2 qb = *reinterpret_cast<const ulonglong2*>(inp + 16 * kk + 8);
        ulonglong2 wI = *reinterpret_cast<const ulonglong2*>(wi + 4 * kk);
        ulonglong2 wG = *reinterpret_cast<const ulonglong2*>(wg + 4 * kk);
        ulonglong2 wO = *reinterpret_cast<const ulonglong2*>(wo + 4 * kk);
        ai0 = fma2(wI.x, qa.x, ai0); ai1 = fma2(wI.x, qa.y, ai1);
        ai0 = fma2(wI.y, qb.x, ai0); ai1 = fma2(wI.y, qb.y, ai1);
        ag0 = fma2(wG.x, qa.x, ag0); ag1 = fma2(wG.x, qa.y, ag1);
        ag0 = fma2(wG.y, qb.x, ag0); ag1 = fma2(wG.y, qb.y, ag1);
        ao0 = fma2(wO.x, qa.x, ao0); ao1 = fma2(wO.x, qa.y, ao1);
        ao0 = fma2(wO.y, qb.x, ao0); ao1 = fma2(wO.y, qb.y, ao1);
        if (HASF) {
            ulonglong2 wF = *reinterpret_cast<const ulonglong2*>(wf + 4 * kk);
            af0 = fma2(wF.x, qa.x, af0); af1 = fma2(wF.x, qa.y, af1);
            af0 = fma2(wF.y, qb.x, af0); af1 = fma2(wF.y, qb.y, af1);
        }
    }
}

#define CMB(a) { ull _o = __shfl_xor_sync(0xffffffffu, a, 16); a = add2(a, _o); }

extern __shared__ float sm[];

__global__ void __launch_bounds__(NTH, 1)
lstm_persist_kernel(const float* __restrict__ x,
                    const float* __restrict__ W1,   const float* __restrict__ b1,
                    const float* __restrict__ Wih1, const float* __restrict__ Whh1,
                    const float* __restrict__ bih1, const float* __restrict__ bhh1,
                    const float* __restrict__ Wih2, const float* __restrict__ Whh2,
                    const float* __restrict__ bih2, const float* __restrict__ bhh2,
                    const float* __restrict__ Wih3, const float* __restrict__ Whh3,
                    const float* __restrict__ bih3, const float* __restrict__ bhh3,
                    const float* __restrict__ W2,   const float* __restrict__ b2,
                    float* __restrict__ out)
{
    const int tid = threadIdx.x;
    const int b0  = blockIdx.x * NB;

    // ---------------- init: weights ----------------
    // stage W1 (1000 floats) inside not-yet-filled WB region
    for (int i = tid; i < HIDN * IN_D; i += NTH) sm[WB_OFF + i] = W1[i];
    __syncthreads();

    // WA x-part: Wc[r][k] = sum_j Wih1[r][j] * W1[j][k]
    for (int i = tid; i < 200 * IN_D; i += NTH) {
        int r = i / IN_D, k = i % IN_D;
        float acc = 0.f;
#pragma unroll 10
        for (int j = 0; j < HIDN; j++)
            acc += Wih1[r * HIDN + j] * sm[WB_OFF + j * IN_D + k];
        sm[WA_OFF + r * WA_STR + k] = acc;
    }
    // WA h-part cols 20..71 (50 real + 2 zero)
    for (int i = tid; i < 200 * 52; i += NTH) {
        int r = i / 52, c = i % 52;
        sm[WA_OFF + r * WA_STR + IN_D + c] = (c < HIDN) ? Whh1[r * HIDN + c] : 0.f;
    }
    __syncthreads();   // staging reads complete before WB fill

    // WB rows: [Wih2(52) | Whh2(52)] + 4 pad (pad never read)
    for (int i = tid; i < 200 * WB_STR; i += NTH) {
        int r = i / WB_STR, c = i % WB_STR;
        float v = 0.f;
        if (c < 52)      { if (c < HIDN) v = Wih2[r * HIDN + c]; }
        else if (c < 104){ int cc = c - 52; if (cc < HIDN) v = Whh2[r * HIDN + cc]; }
        sm[WB_OFF + i] = v;
    }
    // WC rows (150 compact: i, g, o): src row = rr + (rr<50 ? 0 : 50)
    for (int i = tid; i < 150 * WB_STR; i += NTH) {
        int rr = i / WB_STR, c = i % WB_STR;
        int src = rr + ((rr < 50) ? 0 : 50);
        float v = 0.f;
        if (c < 52)      { if (c < HIDN) v = Wih3[src * HIDN + c]; }
        else if (c < 104){ int cc = c - 52; if (cc < HIDN) v = Whh3[src * HIDN + cc]; }
        sm[WC_OFF + i] = v;
    }
    for (int i = tid; i < OUT_D * HIDN; i += NTH) sm[W2_OFF + i] = W2[i];

    // zero all state buffers (XH1, C2, C3 contiguous)
    for (int i = tid; i < SMEM_FLT - XH1_OFF; i += NTH) sm[XH1_OFF + i] = 0.f;
    __syncthreads();
    // x(0) into XH1 parity 1 (step 0 reads rq=1)
    if (tid < NB * IN_D) {
        int b = tid / IN_D, k = tid % IN_D;
        sm[XH1_OFF + 288 + (k >> 1) * 8 + 2 * b + (k & 1)] =
            x[((size_t)(b0 + b) * T_LEN) * IN_D + k];
    }
    __syncthreads();

    // ---------------- role setup ----------------
    const int lane = tid & 31, wrp = tid >> 5;
    const bool ishelp = (wrp == 7);
    const int half = lane >> 4;                 // column half
    const int bp   = (lane >> 3) & 1;           // batch pair
    const int u_raw = wrp * 8 + (lane & 7);     // unit (warps 0-6: 0..55)
    const int u = (u_raw < HIDN) ? u_raw : (HIDN - 1);
    const bool dostore = (!ishelp) && (u_raw < HIDN) && (half == 0);
    // helper mapping: 32 lanes = (batch, out-dim)
    const int ob = lane >> 3, oo = lane & 7;

    // weight pointers (pre-offset by half)
    const float* wa_i = sm + WA_OFF + u * WA_STR + half * 36;
    const float* wa_f = wa_i + 50 * WA_STR;
    const float* wa_g = wa_i + 100 * WA_STR;
    const float* wa_o = wa_i + 150 * WA_STR;
    const float* wb_i = sm + WB_OFF + u * WB_STR + half * 52;
    const float* wb_f = wb_i + 50 * WB_STR;
    const float* wb_g = wb_i + 100 * WB_STR;
    const float* wb_o = wb_i + 150 * WB_STR;
    const float* wc_i = sm + WC_OFF + u * WB_STR + half * 52;
    const float* wc_g = wc_i + 50 * WB_STR;
    const float* wc_o = wc_i + 100 * WB_STR;

    // fused biases (registers; valid for clamped u too)
    float bai = 0, baf = 0, bag = 0, bao = 0;
    float bbi = 0, bbf = 0, bbg = 0, bbo = 0;
    float bci = 0, bcg = 0, bco = 0, b2r = 0;
    if (!ishelp) {
        bai = bih1[u] + bhh1[u];
        baf = bih1[u + 50] + bhh1[u + 50];
        bag = bih1[u + 100] + bhh1[u + 100];
        bao = bih1[u + 150] + bhh1[u + 150];
        for (int j = 0; j < HIDN; j++) {
            float bj = b1[j];
            bai += Wih1[u * HIDN + j] * bj;
            baf += Wih1[(u + 50) * HIDN + j] * bj;
            bag += Wih1[(u + 100) * HIDN + j] * bj;
            bao += Wih1[(u + 150) * HIDN + j] * bj;
        }
        bbi = bih2[u] + bhh2[u];
        bbf = bih2[u + 50] + bhh2[u + 50];
        bbg = bih2[u + 100] + bhh2[u + 100];
        bbo = bih2[u + 150] + bhh2[u + 150];
        bci = bih3[u] + bhh3[u];
        bcg = bih3[u + 100] + bhh3[u + 100];
        bco = bih3[u + 150] + bhh3[u + 150];
    } else {
        b2r = b2[oo];
    }

    const int up8 = (u >> 1) * 8 + (u & 1);     // pair-layout base for unit u
    const int bpo = 4 * bp;
    float c1s[2] = {0.f, 0.f};                  // cell1 state, batches 2bp,2bp+1
    float czs[2] = {0.f, 0.f};                  // cell3 c_new (acts as c2)

    // ---------------- main loop: 3 barriers/step ----------------
    for (int t = 0; t < T_LEN; t++) {
        const int q = t & 1, rq = 1 - q;

        // ---- phase A: cell1 || helper {out(t-1), x(t+1)} ----
        if (!ishelp) {
            ull ai0=0, ai1=0, af0=0, af1=0, ag0=0, ag1=0, ao0=0, ao1=0;
            gemv_half<9, true>(wa_i, wa_f, wa_g, wa_o,
                               sm + XH1_OFF + rq * 288 + half * 144 + bpo,
                               ai0, ai1, af0, af1, ag0, ag1, ao0, ao1);
            CMB(ai0) CMB(ai1) CMB(af0) CMB(af1)
            CMB(ag0) CMB(ag1) CMB(ao0) CMB(ao1)
            float lo, hi, iv, fv, gv, ov;
#pragma unroll
            for (int k = 0; k < 2; k++) {
                ull A = k ? ai1 : ai0, F = k ? af1 : af0;
                ull G = k ? ag1 : ag0, O = k ? ao1 : ao0;
                upk(A, lo, hi); iv = sigm(lo + hi + bai);
                upk(F, lo, hi); fv = sigm(lo + hi + baf);
                upk(G, lo, hi); gv = tanhap(lo + hi + bag);
                upk(O, lo, hi); ov = sigm(lo + hi + bao);
                c1s[k] = fv * c1s[k] + iv * gv;
                float h = ov * tanhap(c1s[k]);
                if (dostore) {
                    int b = 2 * bp + k;
                    sm[XH1_OFF + q * 288 + 80 + up8 + 2 * b] = h;
                    sm[C2_OFF + q * 416 + up8 + 2 * b] = h;
                }
            }
        } else {
            float xv0 = 0.f, xv1 = 0.f, xv2 = 0.f;
            const bool xl = (t + 1 < T_LEN);
            if (xl) {
                { int e = lane;      int b = e / IN_D, k = e % IN_D;
                  xv0 = x[((size_t)(b0 + b) * T_LEN + t + 1) * IN_D + k]; }
                { int e = lane + 32; int b = e / IN_D, k = e % IN_D;
                  xv1 = x[((size_t)(b0 + b) * T_LEN + t + 1) * IN_D + k]; }
                if (lane + 64 < NB * IN_D) {
                  int e = lane + 64; int b = e / IN_D, k = e % IN_D;
                  xv2 = x[((size_t)(b0 + b) * T_LEN + t + 1) * IN_D + k]; }
            }
            if (t > 0) {   // out(t-1): h3 parity (1-q) lives at C3+208+q*416
                const float* h3p = sm + C3_OFF + 208 + q * 416;
                float acc = b2r;
#pragma unroll
                for (int j = 0; j < HIDN; j++)
                    acc += sm[W2_OFF + oo * HIDN + j] *
                           h3p[(j >> 1) * 8 + 2 * ob + (j & 1)];
                out[((size_t)(b0 + ob) * T_LEN + (t - 1)) * OUT_D + oo] = acc;
            }
            if (xl) {      // x(t+1) -> XH1[q] x-part (read at t+1, rq=q)
                { int e = lane;      int b = e / IN_D, k = e % IN_D;
                  sm[XH1_OFF + q * 288 + (k >> 1) * 8 + 2 * b + (k & 1)] = xv0; }
                { int e = lane + 32; int b = e / IN_D, k = e % IN_D;
                  sm[XH1_OFF + q * 288 + (k >> 1) * 8 + 2 * b + (k & 1)] = xv1; }
                if (lane + 64 < NB * IN_D) {
                  int e = lane + 64; int b = e / IN_D, k = e % IN_D;
                  sm[XH1_OFF + q * 288 + (k >> 1) * 8 + 2 * b + (k & 1)] = xv2; }
            }
        }
        __syncthreads();

        // ---- phase B: cell2 (reads [h1[q] | h2a[1-q]] at C2+q*416) ----
        if (!ishelp) {
            ull ai0=0, ai1=0, af0=0, af1=0, ag0=0, ag1=0, ao0=0, ao1=0;
            gemv_half<13, true>(wb_i, wb_f, wb_g, wb_o,
                                sm + C2_OFF + q * 416 + half * 208 + bpo,
                                ai0, ai1, af0, af1, ag0, ag1, ao0, ao1);
            CMB(ai0) CMB(ai1) CMB(af0) CMB(af1)
            CMB(ag0) CMB(ag1) CMB(ao0) CMB(ao1)
            float lo, hi, iv, fv, gv, ov;
#pragma unroll
            for (int k = 0; k < 2; k++) {
                ull A = k ? ai1 : ai0, F = k ? af1 : af0;
                ull G = k ? ag1 : ag0, O = k ? ao1 : ao0;
                upk(A, lo, hi); iv = sigm(lo + hi + bbi);
                upk(F, lo, hi); fv = sigm(lo + hi + bbf);
                upk(G, lo, hi); gv = tanhap(lo + hi + bbg);
                upk(O, lo, hi); ov = sigm(lo + hi + bbo);
                float c2t = fv * czs[k] + iv * gv;
                float h = ov * tanhap(c2t);
                if (dostore) {
                    int b = 2 * bp + k;
                    sm[C2_OFF + 208 + (1 - q) * 416 + up8 + 2 * b] = h;  // h2a[q]
                    sm[C3_OFF + q * 416 + up8 + 2 * b] = h;              // h2b[q]
                }
            }
        }
        __syncthreads();

        // ---- phase C: cell3 (reads [h2b[q] | h3[1-q]] at C3+q*416); no f ----
        if (!ishelp) {
            ull ai0=0, ai1=0, afx0=0, afx1=0, ag0=0, ag1=0, ao0=0, ao1=0;
            gemv_half<13, false>(wc_i, wc_i, wc_g, wc_o,
                                 sm + C3_OFF + q * 416 + half * 208 + bpo,
                                 ai0, ai1, afx0, afx1, ag0, ag1, ao0, ao1);
            CMB(ai0) CMB(ai1) CMB(ag0) CMB(ag1) CMB(ao0) CMB(ao1)
            float lo, hi, iv, gv, ov;
#pragma unroll
            for (int k = 0; k < 2; k++) {
                ull A = k ? ai1 : ai0;
                ull G = k ? ag1 : ag0, O = k ? ao1 : ao0;
                upk(A, lo, hi); iv = sigm(lo + hi + bci);
                upk(G, lo, hi); gv = tanhap(lo + hi + bcg);
                upk(O, lo, hi); ov = sigm(lo + hi + bco);
                czs[k] = iv * gv;
                float h = ov * tanhap(czs[k]);
                if (dostore) {
                    int b = 2 * bp + k;
                    sm[C3_OFF + 208 + (1 - q) * 416 + up8 + 2 * b] = h;  // h3[q]
                }
            }
        }
        __syncthreads();
    }

    // tail: out for t = T_LEN-1 (h3 parity 1 -> C3+208+0*416)
    if (ishelp) {
        const float* h3p = sm + C3_OFF + 208 + (1 - ((T_LEN - 1) & 1)) * 416;
        float acc = b2r;
#pragma unroll
        for (int j = 0; j < HIDN; j++)
            acc += sm[W2_OFF + oo * HIDN + j] *
                   h3p[(j >> 1) * 8 + 2 * ob + (j & 1)];
        out[((size_t)(b0 + ob) * T_LEN + (T_LEN - 1)) * OUT_D + oo] = acc;
    }
}

extern "C" void kernel_launch(void* const* d_in, const int* in_sizes, int n_in,
                              void* d_out, int out_size)
{
    const float* x    = (const float*)d_in[0];
    const float* W1   = (const float*)d_in[1];
    const float* b1   = (const float*)d_in[2];
    const float* Wih1 = (const float*)d_in[3];
    const float* Whh1 = (const float*)d_in[4];
    const float* bih1 = (const float*)d_in[5];
    const float* bhh1 = (const float*)d_in[6];
    const float* Wih2 = (const float*)d_in[7];
    const float* Whh2 = (const float*)d_in[8];
    const float* bih2 = (const float*)d_in[9];
    const float* bhh2 = (const float*)d_in[10];
    const float* Wih3 = (const float*)d_in[11];
    const float* Whh3 = (const float*)d_in[12];
    const float* bih3 = (const float*)d_in[13];
    const float* bhh3 = (const float*)d_in[14];
    const float* W2   = (const float*)d_in[15];
    const float* b2   = (const float*)d_in[16];
    float* out = (float*)d_out;

    const int smem_bytes = SMEM_FLT * sizeof(float);  // 222,560
    cudaFuncSetAttribute(lstm_persist_kernel,
                         cudaFuncAttributeMaxDynamicSharedMemorySize, smem_bytes);

    lstm_persist_kernel<<<NCTA, NTH, smem_bytes>>>(
        x, W1, b1, Wih1, Whh1, bih1, bhh1,
        Wih2, Whh2, bih2, bhh2, Wih3, Whh3, bih3, bhh3,
        W2, b2, out);
}

// round 10
// speedup vs baseline: 1.6620x; 1.0055x over previous
#include <cuda_runtime.h>

// Net_2095944040841: 3-layer LSTM (reference's buggy c-state wiring) on GB300.
// R10 = R9 layout + 2-barrier step pipeline:
//   phase alpha: cell2(t)            || helper {out(t-1), x(t+1) prefetch}
//   phase beta : cell3(t); cell1(t+1)  (independent gemvs overlap tails)
// Prologue runs cell1(0). Same traffic/work as R9; pure latency restructure.

#define T_LEN 1024
#define IN_D  20
#define HIDN  50
#define OUT_D 8
#define NB    4
#define NCTA  128
#define NTH   256

// shared memory layout (float offsets)
#define WA_STR 76            // cell1 row: 20 fused-x + 52 h1 cols (+4 pad)
#define WB_STR 108           // cells2/3 row: 52 + 52 cols (+4 pad)
#define WA_OFF 0             // 200 x 76                  -> 15200
#define WB_OFF 15200         // 200 x 108                 -> 36800
#define WC_OFF 36800         // 150 x 108 (i,g,o rows)    -> 53000
#define W2_OFF 53000         // 8 x 50                    -> 53400
#define XH1_OFF 53400        // 2 x 288: [x(80)|h1(208)] per parity -> 53976
#define C2_OFF  53976        // [h1[0]|h2a[1]|h1[1]|h2a[0]] 4x208   -> 54808
#define C3_OFF  54808        // [h2b[0]|h3[1]|h2b[1]|h3[0]] 4x208   -> 55640
#define SMEM_FLT 55640       // 222,560 bytes

typedef unsigned long long ull;

static __device__ __forceinline__ void upk(ull v, float &a, float &b) {
    asm("mov.b64 {%0,%1}, %2;" : "=f"(a), "=f"(b) : "l"(v));
}
static __device__ __forceinline__ ull fma2(ull a, ull b, ull c) {
    ull d; asm("fma.rn.f32x2 %0, %1, %2, %3;" : "=l"(d) : "l"(a), "l"(b), "l"(c)); return d;
}
static __device__ __forceinline__ ull add2(ull a, ull b) {
    ull d; asm("add.rn.f32x2 %0, %1, %2;" : "=l"(d) : "l"(a), "l"(b)); return d;
}
static __device__ __forceinline__ float tanhap(float x) {
    float t; asm("tanh.approx.f32 %0, %1;" : "=f"(t) : "f"(x)); return t;
}
static __device__ __forceinline__ float sigm(float x) {
    return fmaf(tanhap(0.5f * x), 0.5f, 0.5f);
}

struct Acc8 { ull i0, i1, f0, f1, g0, g1, o0, o1; };

// Half-GEMV: NQ chunks (4 cols each) of 4 (or 3) gate rows x 2 batches.
template<int NQ, bool HASF>
static __device__ __forceinline__ void gemv_half(
    const float* __restrict__ wi, const float* __restrict__ wf,
    const float* __restrict__ wg, const float* __restrict__ wo,
    const float* __restrict__ inp, Acc8 &A)
{
#pragma unroll
    for (int kk = 0; kk < NQ; kk++) {
        ulonglong2 qa = *reinterpret_cast<const ulonglong2*>(inp + 16 * kk);
        ulonglong2 qb = *reinterpret_cast<const ulonglong2*>(inp + 16 * kk + 8);
        ulonglong2 wI = *reinterpret_cast<const ulonglong2*>(wi + 4 * kk);
        ulonglong2 wG = *reinterpret_cast<const ulonglong2*>(wg + 4 * kk);
        ulonglong2 wO = *reinterpret_cast<const ulonglong2*>(wo + 4 * kk);
        A.i0 = fma2(wI.x, qa.x, A.i0); A.i1 = fma2(wI.x, qa.y, A.i1);
        A.i0 = fma2(wI.y, qb.x, A.i0); A.i1 = fma2(wI.y, qb.y, A.i1);
        A.g0 = fma2(wG.x, qa.x, A.g0); A.g1 = fma2(wG.x, qa.y, A.g1);
        A.g0 = fma2(wG.y, qb.x, A.g0); A.g1 = fma2(wG.y, qb.y, A.g1);
        A.o0 = fma2(wO.x, qa.x, A.o0); A.o1 = fma2(wO.x, qa.y, A.o1);
        A.o0 = fma2(wO.y, qb.x, A.o0); A.o1 = fma2(wO.y, qb.y, A.o1);
        if (HASF) {
            ulonglong2 wF = *reinterpret_cast<const ulonglong2*>(wf + 4 * kk);
            A.f0 = fma2(wF.x, qa.x, A.f0); A.f1 = fma2(wF.x, qa.y, A.f1);
            A.f0 = fma2(wF.y, qb.x, A.f0); A.f1 = fma2(wF.y, qb.y, A.f1);
        }
    }
}

#define CMB(a) { ull _o = __shfl_xor_sync(0xffffffffu, a, 16); a = add2(a, _o); }
#define CMB4(A) { CMB(A.i0) CMB(A.i1) CMB(A.f0) CMB(A.f1) CMB(A.g0) CMB(A.g1) CMB(A.o0) CMB(A.o1) }
#define CMB3(A) { CMB(A.i0) CMB(A.i1) CMB(A.g0) CMB(A.g1) CMB(A.o0) CMB(A.o1) }

extern __shared__ float sm[];

__global__ void __launch_bounds__(NTH, 1)
lstm_persist_kernel(const float* __restrict__ x,
                    const float* __restrict__ W1,   const float* __restrict__ b1,
                    const float* __restrict__ Wih1, const float* __restrict__ Whh1,
                    const float* __restrict__ bih1, const float* __restrict__ bhh1,
                    const float* __restrict__ Wih2, const float* __restrict__ Whh2,
                    const float* __restrict__ bih2, const float* __restrict__ bhh2,
                    const float* __restrict__ Wih3, const float* __restrict__ Whh3,
                    const float* __restrict__ bih3, const float* __restrict__ bhh3,
                    const float* __restrict__ W2,   const float* __restrict__ b2,
                    float* __restrict__ out)
{
    const int tid = threadIdx.x;
    const int b0  = blockIdx.x * NB;

    // ---------------- init: weights ----------------
    for (int i = tid; i < HIDN * IN_D; i += NTH) sm[WB_OFF + i] = W1[i];  // stage W1
    __syncthreads();

    for (int i = tid; i < 200 * IN_D; i += NTH) {
        int r = i / IN_D, k = i % IN_D;
        float acc = 0.f;
#pragma unroll 10
        for (int j = 0; j < HIDN; j++)
            acc += Wih1[r * HIDN + j] * sm[WB_OFF + j * IN_D + k];
        sm[WA_OFF + r * WA_STR + k] = acc;
    }
    for (int i = tid; i < 200 * 52; i += NTH) {
        int r = i / 52, c = i % 52;
        sm[WA_OFF + r * WA_STR + IN_D + c] = (c < HIDN) ? Whh1[r * HIDN + c] : 0.f;
    }
    __syncthreads();   // staging reads complete before WB fill

    for (int i = tid; i < 200 * WB_STR; i += NTH) {
        int r = i / WB_STR, c = i % WB_STR;
        float v = 0.f;
        if (c < 52)      { if (c < HIDN) v = Wih2[r * HIDN + c]; }
        else if (c < 104){ int cc = c - 52; if (cc < HIDN) v = Whh2[r * HIDN + cc]; }
        sm[WB_OFF + i] = v;
    }
    for (int i = tid; i < 150 * WB_STR; i += NTH) {
        int rr = i / WB_STR, c = i % WB_STR;
        int src = rr + ((rr < 50) ? 0 : 50);
        float v = 0.f;
        if (c < 52)      { if (c < HIDN) v = Wih3[src * HIDN + c]; }
        else if (c < 104){ int cc = c - 52; if (cc < HIDN) v = Whh3[src * HIDN + cc]; }
        sm[WC_OFF + i] = v;
    }
    for (int i = tid; i < OUT_D * HIDN; i += NTH) sm[W2_OFF + i] = W2[i];

    for (int i = tid; i < SMEM_FLT - XH1_OFF; i += NTH) sm[XH1_OFF + i] = 0.f;
    __syncthreads();
    // x(0) into XH1 slot 1 x-part (prologue cell1(0) reads slot 1)
    if (tid < NB * IN_D) {
        int b = tid / IN_D, k = tid % IN_D;
        sm[XH1_OFF + 288 + (k >> 1) * 8 + 2 * b + (k & 1)] =
            x[((size_t)(b0 + b) * T_LEN) * IN_D + k];
    }
    __syncthreads();

    // ---------------- role setup ----------------
    const int lane = tid & 31, wrp = tid >> 5;
    const bool ishelp = (wrp == 7);
    const int half = lane >> 4;                 // column half
    const int bp   = (lane >> 3) & 1;           // batch pair
    const int u_raw = wrp * 8 + (lane & 7);
    const int u = (u_raw < HIDN) ? u_raw : (HIDN - 1);
    const bool dostore = (!ishelp) && (u_raw < HIDN) && (half == 0);
    const int ob = lane >> 3, oo = lane & 7;    // helper mapping

    const float* wa_i = sm + WA_OFF + u * WA_STR + half * 36;
    const float* wa_f = wa_i + 50 * WA_STR;
    const float* wa_g = wa_i + 100 * WA_STR;
    const float* wa_o = wa_i + 150 * WA_STR;
    const float* wb_i = sm + WB_OFF + u * WB_STR + half * 52;
    const float* wb_f = wb_i + 50 * WB_STR;
    const float* wb_g = wb_i + 100 * WB_STR;
    const float* wb_o = wb_i + 150 * WB_STR;
    const float* wc_i = sm + WC_OFF + u * WB_STR + half * 52;
    const float* wc_g = wc_i + 50 * WB_STR;
    const float* wc_o = wc_i + 100 * WB_STR;

    float bai = 0, baf = 0, bag = 0, bao = 0;
    float bbi = 0, bbf = 0, bbg = 0, bbo = 0;
    float bci = 0, bcg = 0, bco = 0, b2r = 0;
    if (!ishelp) {
        bai = bih1[u] + bhh1[u];
        baf = bih1[u + 50] + bhh1[u + 50];
        bag = bih1[u + 100] + bhh1[u + 100];
        bao = bih1[u + 150] + bhh1[u + 150];
        for (int j = 0; j < HIDN; j++) {
            float bj = b1[j];
            bai += Wih1[u * HIDN + j] * bj;
            baf += Wih1[(u + 50) * HIDN + j] * bj;
            bag += Wih1[(u + 100) * HIDN + j] * bj;
            bao += Wih1[(u + 150) * HIDN + j] * bj;
        }
        bbi = bih2[u] + bhh2[u];
        bbf = bih2[u + 50] + bhh2[u + 50];
        bbg = bih2[u + 100] + bhh2[u + 100];
        bbo = bih2[u + 150] + bhh2[u + 150];
        bci = bih3[u] + bhh3[u];
        bcg = bih3[u + 100] + bhh3[u + 100];
        bco = bih3[u + 150] + bhh3[u + 150];
    } else {
        b2r = b2[oo];
    }

    const int up8 = (u >> 1) * 8 + (u & 1);
    const int bpo = 4 * bp;
    float c1s[2] = {0.f, 0.f};
    float czs[2] = {0.f, 0.f};
    float lo, hi;

    // ---------------- prologue: cell1(0), h1(0) -> parity 0 ----------------
    if (!ishelp) {
        Acc8 A{};
        gemv_half<9, true>(wa_i, wa_f, wa_g, wa_o,
                           sm + XH1_OFF + 288 + half * 144 + bpo, A);
        CMB4(A)
#pragma unroll
        for (int k = 0; k < 2; k++) {
            ull Ai = k ? A.i1 : A.i0, Af = k ? A.f1 : A.f0;
            ull Ag = k ? A.g1 : A.g0, Ao = k ? A.o1 : A.o0;
            upk(Ai, lo, hi); float iv = sigm(lo + hi + bai);
            upk(Af, lo, hi); float fv = sigm(lo + hi + baf);
            upk(Ag, lo, hi); float gv = tanhap(lo + hi + bag);
            upk(Ao, lo, hi); float ov = sigm(lo + hi + bao);
            c1s[k] = fv * c1s[k] + iv * gv;
            float h = ov * tanhap(c1s[k]);
            if (dostore) {
                int b = 2 * bp + k;
                sm[XH1_OFF + 80 + up8 + 2 * b] = h;     // XH1[0].h1
                sm[C2_OFF + up8 + 2 * b] = h;           // C2 h1[0]
            }
        }
    }
    __syncthreads();

    // ---------------- main loop: 2 barriers/step ----------------
    for (int t = 0; t < T_LEN; t++) {
        const int q = t & 1;

        // ---- phase alpha: cell2(t) || helper {out(t-1), x(t+1)} ----
        if (!ishelp) {
            Acc8 A{};
            gemv_half<13, true>(wb_i, wb_f, wb_g, wb_o,
                                sm + C2_OFF + q * 416 + half * 208 + bpo, A);
            CMB4(A)
#pragma unroll
            for (int k = 0; k < 2; k++) {
                ull Ai = k ? A.i1 : A.i0, Af = k ? A.f1 : A.f0;
                ull Ag = k ? A.g1 : A.g0, Ao = k ? A.o1 : A.o0;
                upk(Ai, lo, hi); float iv = sigm(lo + hi + bbi);
                upk(Af, lo, hi); float fv = sigm(lo + hi + bbf);
                upk(Ag, lo, hi); float gv = tanhap(lo + hi + bbg);
                upk(Ao, lo, hi); float ov = sigm(lo + hi + bbo);
                float c2t = fv * czs[k] + iv * gv;
                float h = ov * tanhap(c2t);
                if (dostore) {
                    int b = 2 * bp + k;
                    sm[C2_OFF + 208 + (1 - q) * 416 + up8 + 2 * b] = h;  // h2a[q]
                    sm[C3_OFF + q * 416 + up8 + 2 * b] = h;              // h2b[q]
                }
            }
        } else {
            float xv0 = 0.f, xv1 = 0.f, xv2 = 0.f;
            const bool xl = (t + 1 < T_LEN);
            if (xl) {
                { int e = lane;      int b = e / IN_D, k = e % IN_D;
                  xv0 = x[((size_t)(b0 + b) * T_LEN + t + 1) * IN_D + k]; }
                { int e = lane + 32; int b = e / IN_D, k = e % IN_D;
                  xv1 = x[((size_t)(b0 + b) * T_LEN + t + 1) * IN_D + k]; }
                if (lane + 64 < NB * IN_D) {
                  int e = lane + 64; int b = e / IN_D, k = e % IN_D;
                  xv2 = x[((size_t)(b0 + b) * T_LEN + t + 1) * IN_D + k]; }
            }
            if (t > 0) {   // out(t-1): h3 parity (1-q) at C3+208+q*416
                const float* h3p = sm + C3_OFF + 208 + q * 416;
                float acc = b2r;
#pragma unroll
                for (int j = 0; j < HIDN; j++)
                    acc += sm[W2_OFF + oo * HIDN + j] *
                           h3p[(j >> 1) * 8 + 2 * ob + (j & 1)];
                out[((size_t)(b0 + ob) * T_LEN + (t - 1)) * OUT_D + oo] = acc;
            }
            if (xl) {      // x(t+1) -> XH1[q].x (read in phase beta this step)
                { int e = lane;      int b = e / IN_D, k = e % IN_D;
                  sm[XH1_OFF + q * 288 + (k >> 1) * 8 + 2 * b + (k & 1)] = xv0; }
                { int e = lane + 32; int b = e / IN_D, k = e % IN_D;
                  sm[XH1_OFF + q * 288 + (k >> 1) * 8 + 2 * b + (k & 1)] = xv1; }
                if (lane + 64 < NB * IN_D) {
                  int e = lane + 64; int b = e / IN_D, k = e % IN_D;
                  sm[XH1_OFF + q * 288 + (k >> 1) * 8 + 2 * b + (k & 1)] = xv2; }
            }
        }
        __syncthreads();

        // ---- phase beta: cell3(t) + cell1(t+1) (independent, overlap) ----
        if (!ishelp) {
            Acc8 A3{};
            gemv_half<13, false>(wc_i, wc_i, wc_g, wc_o,
                                 sm + C3_OFF + q * 416 + half * 208 + bpo, A3);
            if (t + 1 < T_LEN) {
                Acc8 A1{};
                gemv_half<9, true>(wa_i, wa_f, wa_g, wa_o,
                                   sm + XH1_OFF + q * 288 + half * 144 + bpo, A1);
                // finish cell3
                CMB3(A3)
#pragma unroll
                for (int k = 0; k < 2; k++) {
                    ull Ai = k ? A3.i1 : A3.i0;
                    ull Ag = k ? A3.g1 : A3.g0, Ao = k ? A3.o1 : A3.o0;
                    upk(Ai, lo, hi); float iv = sigm(lo + hi + bci);
                    upk(Ag, lo, hi); float gv = tanhap(lo + hi + bcg);
                    upk(Ao, lo, hi); float ov = sigm(lo + hi + bco);
                    czs[k] = iv * gv;
                    float h = ov * tanhap(czs[k]);
                    if (dostore)
                        sm[C3_OFF + 208 + (1 - q) * 416 + up8 + 2 * (2 * bp + k)] = h;
                }
                // finish cell1(t+1): h1(t+1) parity 1-q
                CMB4(A1)
#pragma unroll
                for (int k = 0; k < 2; k++) {
                    ull Ai = k ? A1.i1 : A1.i0, Af = k ? A1.f1 : A1.f0;
                    ull Ag = k ? A1.g1 : A1.g0, Ao = k ? A1.o1 : A1.o0;
                    upk(Ai, lo, hi); float iv = sigm(lo + hi + bai);
                    upk(Af, lo, hi); float fv = sigm(lo + hi + baf);
                    upk(Ag, lo, hi); float gv = tanhap(lo + hi + bag);
                    upk(Ao, lo, hi); float ov = sigm(lo + hi + bao);
                    c1s[k] = fv * c1s[k] + iv * gv;
                    float h = ov * tanhap(c1s[k]);
                    if (dostore) {
                        int b = 2 * bp + k;
                        sm[XH1_OFF + (1 - q) * 288 + 80 + up8 + 2 * b] = h;
                        sm[C2_OFF + (1 - q) * 416 + up8 + 2 * b] = h;
                    }
                }
            } else {
                CMB3(A3)
#pragma unroll
                for (int k = 0; k < 2; k++) {
                    ull Ai = k ? A3.i1 : A3.i0;
                    ull Ag = k ? A3.g1 : A3.g0, Ao = k ? A3.o1 : A3.o0;
                    upk(Ai, lo, hi); float iv = sigm(lo + hi + bci);
                    upk(Ag, lo, hi); float gv = tanhap(lo + hi + bcg);
                    upk(Ao, lo, hi); float ov = sigm(lo + hi + bco);
                    czs[k] = iv * gv;
                    float h = ov * tanhap(czs[k]);
                    if (dostore)
                        sm[C3_OFF + 208 + (1 - q) * 416 + up8 + 2 * (2 * bp + k)] = h;
                }
            }
        }
        __syncthreads();
    }

    // epilogue: out(T_LEN-1); h3 parity 1 at C3+208+0*416
    if (ishelp) {
        const float* h3p = sm + C3_OFF + 208;
        float acc = b2r;
#pragma unroll
        for (int j = 0; j < HIDN; j++)
            acc += sm[W2_OFF + oo * HIDN + j] *
                   h3p[(j >> 1) * 8 + 2 * ob + (j & 1)];
        out[((size_t)(b0 + ob) * T_LEN + (T_LEN - 1)) * OUT_D + oo] = acc;
    }
}

extern "C" void kernel_launch(void* const* d_in, const int* in_sizes, int n_in,
                              void* d_out, int out_size)
{
    const float* x    = (const float*)d_in[0];
    const float* W1   = (const float*)d_in[1];
    const float* b1   = (const float*)d_in[2];
    const float* Wih1 = (const float*)d_in[3];
    const float* Whh1 = (const float*)d_in[4];
    const float* bih1 = (const float*)d_in[5];
    const float* bhh1 = (const float*)d_in[6];
    const float* Wih2 = (const float*)d_in[7];
    const float* Whh2 = (const float*)d_in[8];
    const float* bih2 = (const float*)d_in[9];
    const float* bhh2 = (const float*)d_in[10];
    const float* Wih3 = (const float*)d_in[11];
    const float* Whh3 = (const float*)d_in[12];
    const float* bih3 = (const float*)d_in[13];
    const float* bhh3 = (const float*)d_in[14];
    const float* W2   = (const float*)d_in[15];
    const float* b2   = (const float*)d_in[16];
    float* out = (float*)d_out;

    const int smem_bytes = SMEM_FLT * sizeof(float);  // 222,560
    cudaFuncSetAttribute(lstm_persist_kernel,
                         cudaFuncAttributeMaxDynamicSharedMemorySize, smem_bytes);

    lstm_persist_kernel<<<NCTA, NTH, smem_bytes>>>(
        x, W1, b1, Wih1, Whh1, bih1, bhh1,
        Wih2, Whh2, bih2, bhh2, Wih3, Whh3, bih3, bhh3,
        W2, b2, out);
}